// round 1
// baseline (speedup 1.0000x reference)
#include <cuda_runtime.h>
#include <cstdint>

// ---------------------------------------------------------------------------
// Modulated deformable conv (DCNv2) forward, fused sampling + GEMM, fp32.
// B=4, Cin=Cout=256, H=W=64, 3x3, stride=1, pad=1, dil=1, groups=dg=1.
// ---------------------------------------------------------------------------

constexpr int CIN   = 256;
constexpr int COUT  = 256;
constexpr int HH    = 64;
constexpr int WW    = 64;
constexpr int HW    = HH * WW;          // 4096
constexpr int KTAPS = 9;
constexpr int PT    = 32;               // pixels per CTA tile
constexpr int CCH   = 32;               // Cin chunk held in SMEM
constexpr int NTHR  = 256;

// Transposed weights: [k][c][o], contiguous over o for packed A loads.
__device__ float g_Wt[KTAPS * CIN * COUT];

__global__ void transpose_weights_kernel(const float* __restrict__ w)
{
    int i = blockIdx.x * blockDim.x + threadIdx.x;
    if (i >= KTAPS * CIN * COUT) return;
    int o = i % COUT;
    int c = (i / COUT) % CIN;
    int k = i / (COUT * CIN);
    g_Wt[i] = w[(o * CIN + c) * KTAPS + k];
}

// packed f32x2 helpers -------------------------------------------------------
__device__ __forceinline__ unsigned long long pack2(float lo, float hi) {
    unsigned long long d;
    asm("mov.b64 %0, {%1, %2};" : "=l"(d) : "r"(__float_as_uint(lo)), "r"(__float_as_uint(hi)));
    return d;
}
__device__ __forceinline__ unsigned long long packdup(float v) {
    unsigned long long d;
    asm("mov.b64 %0, {%1, %1};" : "=l"(d) : "r"(__float_as_uint(v)));
    return d;
}
__device__ __forceinline__ void ffma2(unsigned long long& d,
                                      unsigned long long a,
                                      unsigned long long b) {
    asm("fma.rn.f32x2 %0, %1, %2, %0;" : "+l"(d) : "l"(a), "l"(b));
}
__device__ __forceinline__ void unpack2(float& lo, float& hi, unsigned long long v) {
    unsigned int l, h;
    asm("mov.b64 {%0, %1}, %2;" : "=r"(l), "=r"(h) : "l"(v));
    lo = __uint_as_float(l); hi = __uint_as_float(h);
}

__global__ __launch_bounds__(NTHR, 2)
void mdcn_kernel(const float* __restrict__ x,
                 const float* __restrict__ off,
                 const float* __restrict__ mask,
                 const float* __restrict__ bias,
                 float* __restrict__ out)
{
    __shared__ float sWt[CCH][COUT];     // 32 KB  A tile   [c][o]
    __shared__ float sVal[CCH][PT];      // 4 KB   B tile   [c][p]
    __shared__ float sCW[4][PT];         // corner weights (mask folded in)
    __shared__ int   sCI[4][PT];         // corner flat indices (clamped)

    const int b    = blockIdx.y;
    const int p0   = blockIdx.x * PT;    // pixel tile base in [0, 4096)
    const int tid  = threadIdx.x;

    const float* xb = x    + (size_t)b * CIN * HW;
    const float* ob = off  + (size_t)b * 2 * KTAPS * HW;
    const float* mb = mask + (size_t)b * KTAPS * HW;

    // micro-tile: thread (rc, cc) computes Cout rows [rc*8, rc*8+8) x px [cc*4, cc*4+4)
    const int rc = tid >> 3;   // 0..31
    const int cc = tid & 7;    // 0..7

    // acc[pair][px] : pair over (o, o+1), packed f32x2
    unsigned long long acc[4][4];
    {
        const float4 bl = *(const float4*)&bias[rc * 8];
        const float4 bh = *(const float4*)&bias[rc * 8 + 4];
        #pragma unroll
        for (int j = 0; j < 4; j++) {
            acc[0][j] = pack2(bl.x, bl.y);
            acc[1][j] = pack2(bl.z, bl.w);
            acc[2][j] = pack2(bh.x, bh.y);
            acc[3][j] = pack2(bh.z, bh.w);
        }
    }

    // gather-role mapping: p fixed per thread, 4 channels per chunk
    const int gp  = tid & 31;          // pixel 0..31
    const int gc8 = (tid >> 5) * 4;    // channel sub-base 0,4,...,28

    for (int k = 0; k < KTAPS; k++) {
        // ---- per-(k,px) bilinear coefficients (one warp) -------------------
        if (tid < PT) {
            const int p  = p0 + tid;
            const int ho = p >> 6;
            const int wo = p & 63;
            const int kh = k / 3;
            const int kw = k - kh * 3;
            const float dy = ob[(2 * k)     * HW + p];
            const float dx = ob[(2 * k + 1) * HW + p];
            const float m  = mb[k * HW + p];
            const float sy = (float)(ho - 1 + kh) + dy;
            const float sx = (float)(wo - 1 + kw) + dx;
            const float y0f = floorf(sy), x0f = floorf(sx);
            const float wy = sy - y0f, wx = sx - x0f;
            const int y0 = (int)y0f, x0i = (int)x0f;
            const int y1 = y0 + 1,  x1 = x0i + 1;
            const float vy0 = (y0 >= 0 && y0 < HH) ? 1.f : 0.f;
            const float vy1 = (y1 >= 0 && y1 < HH) ? 1.f : 0.f;
            const float vx0 = (x0i >= 0 && x0i < WW) ? 1.f : 0.f;
            const float vx1 = (x1 >= 0 && x1 < WW) ? 1.f : 0.f;
            const int cy0 = min(max(y0, 0), HH - 1);
            const int cy1 = min(max(y1, 0), HH - 1);
            const int cx0 = min(max(x0i, 0), WW - 1);
            const int cx1 = min(max(x1, 0), WW - 1);
            sCI[0][tid] = cy0 * WW + cx0;  sCW[0][tid] = (1.f - wy) * (1.f - wx) * m * vy0 * vx0;
            sCI[1][tid] = cy0 * WW + cx1;  sCW[1][tid] = (1.f - wy) * wx         * m * vy0 * vx1;
            sCI[2][tid] = cy1 * WW + cx0;  sCW[2][tid] = wy * (1.f - wx)         * m * vy1 * vx0;
            sCI[3][tid] = cy1 * WW + cx1;  sCW[3][tid] = wy * wx                 * m * vy1 * vx1;
        }
        __syncthreads();

        const float w0 = sCW[0][gp], w1 = sCW[1][gp], w2 = sCW[2][gp], w3 = sCW[3][gp];
        const int   i0 = sCI[0][gp], i1 = sCI[1][gp], i2 = sCI[2][gp], i3 = sCI[3][gp];

        const float* wtk = g_Wt + k * CIN * COUT;

        for (int ch = 0; ch < CIN; ch += CCH) {
            // ---- gather + modulate into B tile -----------------------------
            #pragma unroll
            for (int j = 0; j < 4; j++) {
                const int cl = gc8 + j;
                const float* xc = xb + (ch + cl) * HW;
                sVal[cl][gp] = w0 * __ldg(xc + i0) + w1 * __ldg(xc + i1)
                             + w2 * __ldg(xc + i2) + w3 * __ldg(xc + i3);
            }
            // ---- stream A tile (coalesced float4) --------------------------
            {
                const float4* src = (const float4*)(wtk + ch * COUT);
                float4* dst = (float4*)&sWt[0][0];
                #pragma unroll
                for (int j = 0; j < (CCH * COUT / 4) / NTHR; j++)   // 8 iters
                    dst[tid + j * NTHR] = src[tid + j * NTHR];
            }
            __syncthreads();

            // ---- GEMM micro-kernel: packed f32x2 over Cout pairs -----------
            #pragma unroll 8
            for (int c = 0; c < CCH; c++) {
                const ulonglong2 a01 = *(const ulonglong2*)&sWt[c][rc * 8];     // o0..o3
                const ulonglong2 a23 = *(const ulonglong2*)&sWt[c][rc * 8 + 4]; // o4..o7
                const float4 bv = *(const float4*)&sVal[c][cc * 4];
                const unsigned long long b0 = packdup(bv.x);
                const unsigned long long b1 = packdup(bv.y);
                const unsigned long long b2 = packdup(bv.z);
                const unsigned long long b3 = packdup(bv.w);
                ffma2(acc[0][0], a01.x, b0); ffma2(acc[0][1], a01.x, b1);
                ffma2(acc[0][2], a01.x, b2); ffma2(acc[0][3], a01.x, b3);
                ffma2(acc[1][0], a01.y, b0); ffma2(acc[1][1], a01.y, b1);
                ffma2(acc[1][2], a01.y, b2); ffma2(acc[1][3], a01.y, b3);
                ffma2(acc[2][0], a23.x, b0); ffma2(acc[2][1], a23.x, b1);
                ffma2(acc[2][2], a23.x, b2); ffma2(acc[2][3], a23.x, b3);
                ffma2(acc[3][0], a23.y, b0); ffma2(acc[3][1], a23.y, b1);
                ffma2(acc[3][2], a23.y, b2); ffma2(acc[3][3], a23.y, b3);
            }
            __syncthreads();
        }
    }

    // ---- epilogue: unpack, vectorized store (contiguous over px) ----------
    float* ob_out = out + ((size_t)b * COUT) * HW + p0 + cc * 4;
    #pragma unroll
    for (int pr = 0; pr < 4; pr++) {
        float lo0, hi0, lo1, hi1, lo2, hi2, lo3, hi3;
        unpack2(lo0, hi0, acc[pr][0]);
        unpack2(lo1, hi1, acc[pr][1]);
        unpack2(lo2, hi2, acc[pr][2]);
        unpack2(lo3, hi3, acc[pr][3]);
        const int o_lo = rc * 8 + 2 * pr;
        float4 vlo = make_float4(lo0, lo1, lo2, lo3);
        float4 vhi = make_float4(hi0, hi1, hi2, hi3);
        *(float4*)(ob_out + (size_t)o_lo       * HW) = vlo;
        *(float4*)(ob_out + (size_t)(o_lo + 1) * HW) = vhi;
    }
}

extern "C" void kernel_launch(void* const* d_in, const int* in_sizes, int n_in,
                              void* d_out, int out_size)
{
    const float* x    = (const float*)d_in[0];
    const float* off  = (const float*)d_in[1];
    const float* mask = (const float*)d_in[2];
    const float* w    = (const float*)d_in[3];
    const float* bias = (const float*)d_in[4];
    float* out = (float*)d_out;

    const int B = in_sizes[0] / (CIN * HW);   // 4

    transpose_weights_kernel<<<(KTAPS * CIN * COUT + 255) / 256, 256>>>(w);

    dim3 grid(HW / PT, B);                    // (128, 4)
    mdcn_kernel<<<grid, NTHR>>>(x, off, mask, bias, out);
}

// round 3
// speedup vs baseline: 2.1407x; 2.1407x over previous
#include <cuda_runtime.h>
#include <cuda_bf16.h>
#include <cstdint>

#define DINL __device__ __forceinline__

// ---------------------------------------------------------------------------
// DCNv2 forward via legacy mma.sync bf16-split (3-pass) GEMM. sm_80 PTX only.
// B=4, Cin=Cout=256, H=W=64, 3x3, s=1, p=1, d=1, groups=dg=1.
// out[256,4096] = W[256,2304] x cols[2304,4096] per batch, fused gather.
// ---------------------------------------------------------------------------

constexpr int CIN = 256, COUT = 256, HH = 64, WW = 64, HWp = 4096, KTAPS = 9;
constexpr int NPX    = 128;           // px per CTA (GEMM N)
constexpr int NCHUNK = 36;            // 9 taps x 4 cin-blocks of 64
constexpr int NTHR   = 256;

// Pre-swizzled bf16 weights: [chunk][hi/lo][256 rows][64 cols] = 64KB/chunk
__device__ __align__(16) __nv_bfloat16 g_W[(size_t)NCHUNK * 2 * 256 * 64];

// SMEM layout (bytes)
constexpr int SM_A   = 0;             // A hi @0 (32KB), A lo @32768 (32KB)
constexpr int SM_BH  = 65536;         // B hi 128x128B = 16KB
constexpr int SM_BL  = 81920;         // B lo 16KB
constexpr int SM_CW  = 98304;         // 4*128 floats
constexpr int SM_CI  = 100352;        // 4*128 ints
constexpr int SM_TOTAL = 102400;

// ------------------------------- PTX helpers -------------------------------
DINL uint32_t smem_u32(const void* p) {
    uint32_t a;
    asm("{ .reg .u64 t; cvta.to.shared.u64 t, %1; cvt.u32.u64 %0, t; }"
        : "=r"(a) : "l"(p));
    return a;
}
DINL void ldsm4(uint32_t& r0, uint32_t& r1, uint32_t& r2, uint32_t& r3, uint32_t a) {
    asm volatile("ldmatrix.sync.aligned.m8n8.x4.shared.b16 {%0,%1,%2,%3}, [%4];"
                 : "=r"(r0), "=r"(r1), "=r"(r2), "=r"(r3) : "r"(a));
}
DINL void mma_bf16(float* d, const uint32_t* a, const uint32_t* b) {
    asm volatile(
        "mma.sync.aligned.m16n8k16.row.col.f32.bf16.bf16.f32 "
        "{%0,%1,%2,%3},{%4,%5,%6,%7},{%8,%9},{%0,%1,%2,%3};"
        : "+f"(d[0]), "+f"(d[1]), "+f"(d[2]), "+f"(d[3])
        : "r"(a[0]), "r"(a[1]), "r"(a[2]), "r"(a[3]), "r"(b[0]), "r"(b[1]));
}
DINL uint32_t bf2(float hi, float lo) {   // low 16 bits <- lo
    uint32_t r;
    asm("cvt.rn.bf16x2.f32 %0, %1, %2;" : "=r"(r) : "f"(hi), "f"(lo));
    return r;
}

// --------------------------- weight prep kernel -----------------------------
__global__ void prep_weights(const float* __restrict__ w)
{
    int i = blockIdx.x * blockDim.x + threadIdx.x;   // over 36*256*64
    if (i >= NCHUNK * 256 * 64) return;
    int j  = i & 63;            // cin within chunk
    int o  = (i >> 6) & 255;    // cout row
    int ch = i >> 14;           // chunk
    int tap = ch >> 2, cb = ch & 3;
    int c = cb * 64 + j;
    float v = w[((size_t)o * CIN + c) * KTAPS + tap];
    __nv_bfloat16 hi = __float2bfloat16(v);
    __nv_bfloat16 lo = __float2bfloat16(v - __bfloat162float(hi));
    uint32_t swb = ((uint32_t)(j * 2)) ^ (((uint32_t)o & 7u) << 4);  // swizzled byte
    size_t base = (size_t)ch * 32768 + (size_t)o * 64 + (swb >> 1);
    g_W[base]         = hi;
    g_W[base + 16384] = lo;     // lo plane 256*64 elements later
}

// -------------------------------- main kernel -------------------------------
__global__ __launch_bounds__(NTHR)
void mdcn_hmma(const float* __restrict__ x, const float* __restrict__ offp,
               const float* __restrict__ maskp, const float* __restrict__ bias,
               float* __restrict__ out)
{
    extern __shared__ char smem[];
    const uint32_t sb = smem_u32(smem);
    const int tid  = threadIdx.x;
    const int wid  = tid >> 5, lane = tid & 31;

    const int b  = blockIdx.x >> 5;
    const int p0 = (blockIdx.x & 31) * NPX;
    const float* xb = x     + (size_t)b * CIN * HWp;
    const float* ob = offp  + (size_t)b * 2 * KTAPS * HWp;
    const float* mb = maskp + (size_t)b * KTAPS * HWp;

    float* sCW = (float*)(smem + SM_CW);
    int*   sCI = (int*)(smem + SM_CI);

    // gather role: fixed pixel + cin half
    const int px    = tid & 127;
    const int chalf = tid >> 7;              // 0/1 -> cin 0..31 / 32..63

    // mma role
    const int m_w = (wid & 3) * 64;          // warp M offset
    const int n_w = (wid >> 2) * 64;         // warp N offset
    // per-lane ldmatrix A address pieces
    const int a_rowpart = (lane & 7) + ((lane >> 3) & 1) * 8;   // 0..15
    const int a_colsel  = ((lane >> 4) & 1) * 16;               // 0/16 bytes
    const uint32_t a_swx = (uint32_t)(lane & 7) << 4;
    // per-lane B address pieces
    const int b_row  = lane >> 2;            // 0..7 within n8 tile
    const uint32_t b_swx = (uint32_t)(b_row & 7) << 4;
    const uint32_t b_kc  = (uint32_t)(lane & 3) * 4;

    float acc[4][8][4];
    #pragma unroll
    for (int i = 0; i < 4; i++)
        #pragma unroll
        for (int j = 0; j < 8; j++)
            #pragma unroll
            for (int q = 0; q < 4; q++) acc[i][j][q] = 0.f;

    for (int ch = 0; ch < NCHUNK; ch++) {
        const int tap = ch >> 2, cb = ch & 3;

        // ---- per-tap bilinear corner tables --------------------------------
        if (cb == 0) {
            __syncthreads();     // previous mma reads done before table rewrite
            if (tid < 128) {
                const int p  = p0 + tid;
                const int ho = p >> 6, wo = p & 63;
                const int kh = tap / 3, kw = tap - kh * 3;
                const float dy = ob[(2 * tap)     * HWp + p];
                const float dx = ob[(2 * tap + 1) * HWp + p];
                const float m  = mb[tap * HWp + p];
                const float sy = (float)(ho - 1 + kh) + dy;
                const float sx = (float)(wo - 1 + kw) + dx;
                const float y0f = floorf(sy), x0f = floorf(sx);
                const float wy = sy - y0f, wx = sx - x0f;
                const int y0 = (int)y0f, x0 = (int)x0f;
                const int y1 = y0 + 1, x1 = x0 + 1;
                const float vy0 = (y0 >= 0 && y0 < HH) ? 1.f : 0.f;
                const float vy1 = (y1 >= 0 && y1 < HH) ? 1.f : 0.f;
                const float vx0 = (x0 >= 0 && x0 < WW) ? 1.f : 0.f;
                const float vx1 = (x1 >= 0 && x1 < WW) ? 1.f : 0.f;
                const int cy0 = min(max(y0, 0), HH - 1);
                const int cy1 = min(max(y1, 0), HH - 1);
                const int cx0 = min(max(x0, 0), WW - 1);
                const int cx1 = min(max(x1, 0), WW - 1);
                sCI[tid]       = cy0 * WW + cx0;
                sCI[128 + tid] = cy0 * WW + cx1;
                sCI[256 + tid] = cy1 * WW + cx0;
                sCI[384 + tid] = cy1 * WW + cx1;
                sCW[tid]       = (1.f - wy) * (1.f - wx) * m * vy0 * vx0;
                sCW[128 + tid] = (1.f - wy) * wx         * m * vy0 * vx1;
                sCW[256 + tid] = wy * (1.f - wx)         * m * vy1 * vx0;
                sCW[384 + tid] = wy * wx                 * m * vy1 * vx1;
            }
        }
        __syncthreads();   // tables ready / previous mma reads done (WAR)

        // ---- A tile copy: 64KB pre-swizzled hi+lo --------------------------
        {
            const uint4* src = (const uint4*)(g_W + (size_t)ch * 32768);
            uint4* dst = (uint4*)(smem + SM_A);
            #pragma unroll
            for (int t = 0; t < 16; t++)
                dst[tid + t * 256] = src[tid + t * 256];
        }

        // ---- B gather: 128 px x 64 cin -> swizzled bf16 hi/lo --------------
        {
            const float w0 = sCW[px],       w1 = sCW[128 + px];
            const float w2 = sCW[256 + px], w3 = sCW[384 + px];
            const int   i0 = sCI[px],       i1 = sCI[128 + px];
            const int   i2 = sCI[256 + px], i3 = sCI[384 + px];
            const float* xc = xb + (size_t)(cb * 64 + chalf * 32) * HWp;
            char* rowH = smem + SM_BH + px * 128;
            char* rowL = smem + SM_BL + px * 128;
            const uint32_t psw = ((uint32_t)px & 7u) << 4;
            #pragma unroll
            for (int j = 0; j < 16; j++) {
                const float* pA = xc + (size_t)(2 * j) * HWp;
                const float* pB = pA + HWp;
                float a0 = w0 * __ldg(pA + i0) + w1 * __ldg(pA + i1)
                         + w2 * __ldg(pA + i2) + w3 * __ldg(pA + i3);
                float a1 = w0 * __ldg(pB + i0) + w1 * __ldg(pB + i1)
                         + w2 * __ldg(pB + i2) + w3 * __ldg(pB + i3);
                float h0 = __bfloat162float(__float2bfloat16(a0));
                float h1 = __bfloat162float(__float2bfloat16(a1));
                const uint32_t cby = (uint32_t)((chalf * 32 + 2 * j) * 2) ^ psw;
                *(uint32_t*)(rowH + cby) = bf2(a1, a0);
                *(uint32_t*)(rowL + cby) = bf2(a1 - h1, a0 - h0);
            }
        }
        __syncthreads();

        // ---- 3-pass split MMA over 4 k16 steps -----------------------------
        const uint32_t sAhi = sb + SM_A;
        const uint32_t sAlo = sb + SM_A + 32768;
        const uint32_t sBhi = sb + SM_BH;
        const uint32_t sBlo = sb + SM_BL;
        const uint32_t aRow = (uint32_t)(m_w + a_rowpart) * 128u;
        const uint32_t bRow = (uint32_t)(n_w + b_row) * 128u;

        #pragma unroll
        for (int ks = 0; ks < 4; ks++) {
            const uint32_t kb = (uint32_t)ks * 32u;
            const uint32_t aCol = (kb + (uint32_t)a_colsel) ^ a_swx;
            uint32_t ah[4][4], bh[8][2], bl[8][2];
            #pragma unroll
            for (int im = 0; im < 4; im++)
                ldsm4(ah[im][0], ah[im][1], ah[im][2], ah[im][3],
                      sAhi + aRow + (uint32_t)im * 2048u + aCol);
            #pragma unroll
            for (int in = 0; in < 8; in++) {
                const uint32_t base = bRow + (uint32_t)in * 1024u;
                bh[in][0] = *(const uint32_t*)(smem + (SM_BH + base + ((kb + b_kc) ^ b_swx)));
                bh[in][1] = *(const uint32_t*)(smem + (SM_BH + base + ((kb + 16 + b_kc) ^ b_swx)));
            }
            #pragma unroll
            for (int im = 0; im < 4; im++)
                #pragma unroll
                for (int in = 0; in < 8; in++)
                    mma_bf16(acc[im][in], ah[im], bh[in]);   // hi*hi
            #pragma unroll
            for (int in = 0; in < 8; in++) {
                const uint32_t base = bRow + (uint32_t)in * 1024u;
                bl[in][0] = *(const uint32_t*)(smem + (SM_BL + base + ((kb + b_kc) ^ b_swx)));
                bl[in][1] = *(const uint32_t*)(smem + (SM_BL + base + ((kb + 16 + b_kc) ^ b_swx)));
            }
            #pragma unroll
            for (int im = 0; im < 4; im++)
                #pragma unroll
                for (int in = 0; in < 8; in++)
                    mma_bf16(acc[im][in], ah[im], bl[in]);   // hi*lo
            #pragma unroll
            for (int im = 0; im < 4; im++)
                ldsm4(ah[im][0], ah[im][1], ah[im][2], ah[im][3],
                      sAlo + aRow + (uint32_t)im * 2048u + aCol);   // A-lo
            #pragma unroll
            for (int im = 0; im < 4; im++)
                #pragma unroll
                for (int in = 0; in < 8; in++)
                    mma_bf16(acc[im][in], ah[im], bh[in]);   // lo*hi
        }
        (void)sBhi; (void)sBlo;
    }

    // ---- epilogue: bias + store -------------------------------------------
    #pragma unroll
    for (int im = 0; im < 4; im++) {
        const int r0 = m_w + im * 16 + (lane >> 2);
        const int r1 = r0 + 8;
        const float bv0 = __ldg(bias + r0);
        const float bv1 = __ldg(bias + r1);
        float* o0 = out + ((size_t)b * COUT + r0) * HWp + p0 + n_w + 2 * (lane & 3);
        float* o1 = out + ((size_t)b * COUT + r1) * HWp + p0 + n_w + 2 * (lane & 3);
        #pragma unroll
        for (int in = 0; in < 8; in++) {
            float2 v0 = make_float2(acc[im][in][0] + bv0, acc[im][in][1] + bv0);
            float2 v1 = make_float2(acc[im][in][2] + bv1, acc[im][in][3] + bv1);
            *(float2*)(o0 + in * 8) = v0;
            *(float2*)(o1 + in * 8) = v1;
        }
    }
}

// ------------------------------- launch -------------------------------------
extern "C" void kernel_launch(void* const* d_in, const int* in_sizes, int n_in,
                              void* d_out, int out_size)
{
    const float* x    = (const float*)d_in[0];
    const float* off  = (const float*)d_in[1];
    const float* mask = (const float*)d_in[2];
    const float* w    = (const float*)d_in[3];
    const float* bias = (const float*)d_in[4];
    float* out = (float*)d_out;

    cudaFuncSetAttribute(mdcn_hmma, cudaFuncAttributeMaxDynamicSharedMemorySize, SM_TOTAL);

    prep_weights<<<(NCHUNK * 256 * 64 + 255) / 256, 256>>>(w);

    const int B = in_sizes[0] / (CIN * HWp);      // 4
    mdcn_hmma<<<B * (HWp / NPX), NTHR, SM_TOTAL>>>(x, off, mask, bias, out);
}